// round 12
// baseline (speedup 1.0000x reference)
#include <cuda_runtime.h>
#include <cuda_fp16.h>
#include <cstdint>

#define B_SZ   8192
#define D_IN   5000
#define H_SZ   512
#define T_SZ   16
#define K1PAD  5120
#define K3     8192

// ---------------- device scratch (static; no runtime allocation) ------------
__device__ __half gA1h[(size_t)B_SZ * K1PAD];
__device__ __half gA1l[(size_t)B_SZ * K1PAD];
__device__ __half gB1h[(size_t)H_SZ * K1PAD];
__device__ __half gB1l[(size_t)H_SZ * K1PAD];
__device__ __half gA3h[(size_t)B_SZ * K3];
__device__ __half gA3l[(size_t)B_SZ * K3];
__device__ __half gB3h[(size_t)H_SZ * K3];
__device__ __half gB3l[(size_t)H_SZ * K3];
__device__ float g_mlp_out[(size_t)B_SZ * H_SZ];
__device__ float g_out1[(size_t)B_SZ * H_SZ];

// ---------------- helpers ----------------------------------------------------
__device__ __forceinline__ uint32_t smem_u32(const void* p) {
    uint32_t a;
    asm("{ .reg .u64 t; cvta.to.shared.u64 t, %1; cvt.u32.u64 %0, t; }"
        : "=r"(a) : "l"(p));
    return a;
}

__device__ __forceinline__ void cpa16(uint32_t d, const void* s) {
    asm volatile("cp.async.cg.shared.global [%0], [%1], 16;" :: "r"(d), "l"(s));
}
#define CP_COMMIT() asm volatile("cp.async.commit_group;" ::: "memory")
#define CP_WAIT1()  asm volatile("cp.async.wait_group 1;" ::: "memory")

__device__ __forceinline__ void ldsm4(uint32_t* r, uint32_t a) {
    asm volatile("ldmatrix.sync.aligned.m8n8.x4.shared.b16 {%0,%1,%2,%3}, [%4];"
                 : "=r"(r[0]), "=r"(r[1]), "=r"(r[2]), "=r"(r[3]) : "r"(a));
}

__device__ __forceinline__ void mma16816(float* c, const uint32_t* a,
                                         uint32_t b0, uint32_t b1) {
    asm volatile(
        "mma.sync.aligned.m16n8k16.row.col.f32.f16.f16.f32 "
        "{%0,%1,%2,%3}, {%4,%5,%6,%7}, {%8,%9}, {%0,%1,%2,%3};"
        : "+f"(c[0]), "+f"(c[1]), "+f"(c[2]), "+f"(c[3])
        : "r"(a[0]), "r"(a[1]), "r"(a[2]), "r"(a[3]), "r"(b0), "r"(b1));
}

// ---------------- split helpers ---------------------------------------------
__device__ __forceinline__ void split4h_store(__half* ph, __half* pl,
                                              size_t off, float4 v) {
    union { __half b[4]; uint2 u; } H, L;
    float x[4] = {v.x, v.y, v.z, v.w};
#pragma unroll
    for (int i = 0; i < 4; ++i) {
        __half h = __float2half_rn(x[i]);
        H.b[i] = h;
        L.b[i] = __float2half_rn(x[i] - __half2float(h));
    }
    *(uint2*)(ph + off) = H.u;
    *(uint2*)(pl + off) = L.u;
}

__device__ __forceinline__ void split2h_store(__half* ph, __half* pl,
                                              size_t off, float a, float b) {
    union { __half h[2]; uint32_t u; } H, L;
    __half ha = __float2half_rn(a);
    __half hb = __float2half_rn(b);
    H.h[0] = ha; H.h[1] = hb;
    L.h[0] = __float2half_rn(a - __half2float(ha));
    L.h[1] = __float2half_rn(b - __half2float(hb));
    *(uint32_t*)(ph + off) = H.u;
    *(uint32_t*)(pl + off) = L.u;
}

// ---------------- prep kernels ----------------------------------------------
__global__ void prep_A1(const float* __restrict__ x) {
    long idx = (long)blockIdx.x * 256 + threadIdx.x;
    int b  = (int)(idx / (K1PAD / 4));
    int c4 = (int)(idx % (K1PAD / 4));
    int c = c4 * 4;
    float4 v = make_float4(0.f, 0.f, 0.f, 0.f);
    if (c < D_IN) v = *(const float4*)(x + (size_t)b * D_IN + c);
    split4h_store(gA1h, gA1l, (size_t)b * K1PAD + c, v);
}

__global__ void prep_B1(const float* __restrict__ w) {
    long idx = (long)blockIdx.x * 256 + threadIdx.x;
    int n  = (int)(idx / (K1PAD / 4));
    int c4 = (int)(idx % (K1PAD / 4));
    int c = c4 * 4;
    float4 v = make_float4(0.f, 0.f, 0.f, 0.f);
    if (c < D_IN) v = *(const float4*)(w + (size_t)n * D_IN + c);
    split4h_store(gB1h, gB1l, (size_t)n * K1PAD + c, v);
}

// CM [K3=8192][H=512] -> gB3 [H=512][K3=8192] (transpose + split)
__global__ void prep_B3(const float* __restrict__ CM) {
    __shared__ float tile[32][33];
    int k0 = blockIdx.x * 32;
    int n0 = blockIdx.y * 32;
    int tx = threadIdx.x, ty = threadIdx.y;
#pragma unroll
    for (int j = 0; j < 32; j += 8)
        tile[ty + j][tx] = CM[(size_t)(k0 + ty + j) * H_SZ + n0 + tx];
    __syncthreads();
#pragma unroll
    for (int j = 0; j < 32; j += 8) {
        float v = tile[tx][ty + j];
        __half h = __float2half_rn(v);
        __half l = __float2half_rn(v - __half2float(h));
        size_t o = (size_t)(n0 + ty + j) * K3 + k0 + tx;
        gB3h[o] = h;
        gB3l[o] = l;
    }
}

// ---------------- HMMA GEMM --------------------------------------------------
// C[M=8192, N=512] = A @ B^T, fp16 split-2 (hi*hi + hi*lo + lo*hi), fp32 acc.
// CTA tile 64x128, BK=32, 2-stage cp.async pipeline, 8 warps (2M x 4N),
// warp tile 32x32. Smem: 64B rows, XOR swizzle (chunk ^= (row>>1)&3).
// Stage 24KB, 2 stages = 48KB -> 4 CTAs/SM at 64 regs (launch_bounds 256,4).
// Grid 512 CTAs <= 592 slots -> SINGLE WAVE.
#define BM 64
#define BN 128
#define BK 32
#define ROWB 64
#define PLANE_A (BM * ROWB)                 // 4096
#define PLANE_B (BN * ROWB)                 // 8192
#define STAGE (2 * PLANE_A + 2 * PLANE_B)   // 24576
#define OFF_AH 0
#define OFF_AL PLANE_A
#define OFF_BH (2 * PLANE_A)
#define OFF_BL (2 * PLANE_A + PLANE_B)
#define NSTAGE 2
#define SMEM_TOTAL (NSTAGE * STAGE)

__device__ __forceinline__ void load_stage(uint32_t st,
                                           const __half* __restrict__ Ah,
                                           const __half* __restrict__ Al,
                                           const __half* __restrict__ Bh,
                                           const __half* __restrict__ Bl,
                                           int m0, int n0, int K, int k0,
                                           int tid) {
    // A: 64 rows x 4 chunks = 256 ops per plane
    {
        const int r = tid >> 2;
        const int c = tid & 3;
        const int sw = (r >> 1) & 3;
        const uint32_t o = (uint32_t)r * ROWB + (uint32_t)((c ^ sw) << 4);
        const size_t g = (size_t)(m0 + r) * K + k0 + c * 8;
        cpa16(st + OFF_AH + o, Ah + g);
        cpa16(st + OFF_AL + o, Al + g);
    }
    // B: 128 rows x 4 chunks = 512 ops per plane
#pragma unroll
    for (int j = 0; j < 2; ++j) {
        const int i = tid + j * 256;
        const int r = i >> 2;
        const int c = i & 3;
        const int sw = (r >> 1) & 3;
        const uint32_t o = (uint32_t)r * ROWB + (uint32_t)((c ^ sw) << 4);
        const size_t g = (size_t)(n0 + r) * K + k0 + c * 8;
        cpa16(st + OFF_BH + o, Bh + g);
        cpa16(st + OFF_BL + o, Bl + g);
    }
}

template <int MODE>
__global__ void __launch_bounds__(256, 4)
gemm_hmma(const float* __restrict__ bias) {
    extern __shared__ char smem[];
    const uint32_t sb = smem_u32(smem);
    const int tid = threadIdx.x;
    const int wid = tid >> 5, lane = tid & 31;
    const int wm = wid >> 2;            // 0..1  (M)
    const int wn = wid & 3;             // 0..3  (N)

    const int K  = (MODE == 0) ? K1PAD : K3;
    const int nt = K / BK;
    const __half* Ah = (MODE == 0) ? gA1h : gA3h;
    const __half* Al = (MODE == 0) ? gA1l : gA3l;
    const __half* Bh = (MODE == 0) ? gB1h : gB3h;
    const __half* Bl = (MODE == 0) ? gB1l : gB3l;
    float* __restrict__ C = (MODE == 0) ? g_mlp_out : g_out1;

    const int m0 = blockIdx.y * BM;
    const int n0 = blockIdx.x * BN;

    float acc[2][4][4];                 // [mf][nb*2+half][4]
#pragma unroll
    for (int i = 0; i < 2; ++i)
#pragma unroll
        for (int j = 0; j < 4; ++j)
#pragma unroll
            for (int q = 0; q < 4; ++q) acc[i][j][q] = 0.f;

    const int lrow = lane & 15;
    const int lk   = lane >> 4;

    uint32_t aro[2], asw[2];
#pragma unroll
    for (int mf = 0; mf < 2; ++mf) {
        int row = wm * 32 + mf * 16 + lrow;
        aro[mf] = (uint32_t)row * ROWB;
        asw[mf] = (uint32_t)(((row >> 1) & 3) << 4);
    }
    uint32_t bro[2], bsw[2];
#pragma unroll
    for (int nb = 0; nb < 2; ++nb) {
        int row = wn * 32 + nb * 16 + lrow;
        bro[nb] = (uint32_t)row * ROWB;
        bsw[nb] = (uint32_t)(((row >> 1) & 3) << 4);
    }

    // prologue: stage 0 in flight
    load_stage(sb, Ah, Al, Bh, Bl, m0, n0, K, 0, tid);
    CP_COMMIT();

    for (int i = 0; i < nt; ++i) {
        // issue next stage's loads (overlaps with compute of stage i)
        if (i + 1 < nt)
            load_stage(sb + (uint32_t)((i + 1) & 1) * STAGE,
                       Ah, Al, Bh, Bl, m0, n0, K, (i + 1) * BK, tid);
        CP_COMMIT();
        CP_WAIT1();               // stage i resident (i+1 may be in flight)
        __syncthreads();

        const uint32_t st = sb + (uint32_t)(i & 1) * STAGE;

#pragma unroll
        for (int ks = 0; ks < 2; ++ks) {
            const uint32_t cid = (uint32_t)((ks * 2 + lk) << 4);
            uint32_t aH[2][4], aL[2][4];
#pragma unroll
            for (int mf = 0; mf < 2; ++mf) {
                const uint32_t ro = aro[mf] + (cid ^ asw[mf]);
                ldsm4(aH[mf], st + OFF_AH + ro);
                ldsm4(aL[mf], st + OFF_AL + ro);
            }
#pragma unroll
            for (int nb = 0; nb < 2; ++nb) {
                uint32_t bH[4], bL[4];
                const uint32_t ro = bro[nb] + (cid ^ bsw[nb]);
                ldsm4(bH, st + OFF_BH + ro);
                ldsm4(bL, st + OFF_BL + ro);
#pragma unroll
                for (int mf = 0; mf < 2; ++mf) {
                    mma16816(acc[mf][nb * 2],     aH[mf], bH[0], bH[2]);
                    mma16816(acc[mf][nb * 2 + 1], aH[mf], bH[1], bH[3]);
                    mma16816(acc[mf][nb * 2],     aH[mf], bL[0], bL[2]);
                    mma16816(acc[mf][nb * 2 + 1], aH[mf], bL[1], bL[3]);
                    mma16816(acc[mf][nb * 2],     aL[mf], bH[0], bH[2]);
                    mma16816(acc[mf][nb * 2 + 1], aL[mf], bH[1], bH[3]);
                }
            }
        }
        __syncthreads();          // all warps done with stage i before overwrite
    }

    // epilogue
    const int gid = lane >> 2;
    const int tig = lane & 3;
#pragma unroll
    for (int mf = 0; mf < 2; ++mf) {
#pragma unroll
        for (int nf = 0; nf < 4; ++nf) {
            const int nb = nf >> 1, half = nf & 1;
            const int row = m0 + wm * 32 + mf * 16 + gid;
            const int col = n0 + wn * 32 + nb * 16 + half * 8 + 2 * tig;
            float2 v0 = make_float2(acc[mf][nf][0], acc[mf][nf][1]);
            float2 v1 = make_float2(acc[mf][nf][2], acc[mf][nf][3]);
            if (MODE == 0) {
                v0.x += bias[col]; v0.y += bias[col + 1];
                v1.x += bias[col]; v1.y += bias[col + 1];
            }
            *(float2*)(C + (size_t)row * H_SZ + col)       = v0;
            *(float2*)(C + (size_t)(row + 8) * H_SZ + col) = v1;
        }
    }
}

// ---------------- softmax over tasks + fused A3 build ------------------------
__global__ void attn_softmax_kernel(const float* __restrict__ attn) {
    __shared__ float row[H_SZ];
    __shared__ float s[T_SZ];
    __shared__ float wsh[T_SZ];
    const int b = blockIdx.x;
    const int tid = threadIdx.x;
    ((float2*)row)[tid] = ((const float2*)(g_mlp_out + (size_t)b * H_SZ))[tid];
    __syncthreads();
    const int warp = tid >> 5, lane = tid & 31;
#pragma unroll
    for (int tt = 0; tt < 2; ++tt) {
        const int t = warp * 2 + tt;
        float acc = 0.f;
#pragma unroll 4
        for (int h = lane; h < H_SZ; h += 32) acc += row[h] * attn[h * T_SZ + t];
#pragma unroll
        for (int o = 16; o; o >>= 1) acc += __shfl_xor_sync(0xffffffffu, acc, o);
        if (lane == 0) s[t] = acc;
    }
    __syncthreads();
    if (tid == 0) {
        float mx = s[0];
#pragma unroll
        for (int t = 1; t < T_SZ; ++t) mx = fmaxf(mx, s[t]);
        float e[T_SZ];
        float sum = 0.f;
#pragma unroll
        for (int t = 0; t < T_SZ; ++t) { e[t] = __expf(s[t] - mx); sum += e[t]; }
        float inv = 1.f / sum;
#pragma unroll
        for (int t = 0; t < T_SZ; ++t) wsh[t] = e[t] * inv;
    }
    __syncthreads();
    const float2 m2 = ((const float2*)row)[tid];
    const size_t base = (size_t)b * K3 + 2 * tid;
#pragma unroll
    for (int t = 0; t < T_SZ; ++t) {
        const float wv = wsh[t];
        split2h_store(gA3h, gA3l, base + (size_t)t * H_SZ,
                      m2.x * wv, m2.y * wv);
    }
}

// ---------------- classifier + sigmoid --------------------------------------
__global__ void final_kernel(const float* __restrict__ cla_w,
                             const float* __restrict__ cla_b,
                             float* __restrict__ out) {
    const int gw = (blockIdx.x * blockDim.x + threadIdx.x) >> 5;
    const int lane = threadIdx.x & 31;
    if (gw >= B_SZ) return;
    const float4* rp = (const float4*)(g_out1 + (size_t)gw * H_SZ);
    const float4* wp = (const float4*)cla_w;
    float acc = 0.f;
#pragma unroll
    for (int i = lane; i < H_SZ / 4; i += 32) {
        float4 a = rp[i], w = wp[i];
        acc += a.x * w.x + a.y * w.y + a.z * w.z + a.w * w.w;
    }
#pragma unroll
    for (int o = 16; o; o >>= 1) acc += __shfl_xor_sync(0xffffffffu, acc, o);
    if (lane == 0) {
        float logit = acc + cla_b[0];
        out[gw] = 1.f / (1.f + __expf(-logit));
    }
}

// ---------------- launch -----------------------------------------------------
extern "C" void kernel_launch(void* const* d_in, const int* in_sizes, int n_in,
                              void* d_out, int out_size) {
    const float* data_input = (const float*)d_in[0];
    const float* mlp_w      = (const float*)d_in[1];
    const float* mlp_b      = (const float*)d_in[2];
    const float* CM         = (const float*)d_in[3];
    const float* attn       = (const float*)d_in[4];
    const float* cla_w      = (const float*)d_in[5];
    const float* cla_b      = (const float*)d_in[6];
    float* out = (float*)d_out;

    cudaFuncSetAttribute(gemm_hmma<0>, cudaFuncAttributeMaxDynamicSharedMemorySize,
                         SMEM_TOTAL);
    cudaFuncSetAttribute(gemm_hmma<1>, cudaFuncAttributeMaxDynamicSharedMemorySize,
                         SMEM_TOTAL);

    // input conversions
    prep_A1<<<(B_SZ * (K1PAD / 4)) / 256, 256>>>(data_input);
    prep_B1<<<(H_SZ * (K1PAD / 4)) / 256, 256>>>(mlp_w);
    prep_B3<<<dim3(K3 / 32, H_SZ / 32), dim3(32, 8)>>>(CM);

    // GEMM1: mlp_out = data @ mlp_w^T + b   (512 CTAs, single wave @ 4/SM)
    gemm_hmma<0><<<dim3(H_SZ / BN, B_SZ / BM), 256, SMEM_TOTAL>>>(mlp_b);

    // softmax task weights + fused A' split build
    attn_softmax_kernel<<<B_SZ, 256>>>(attn);

    // GEMM3: out1 = A' @ CM^T
    gemm_hmma<1><<<dim3(H_SZ / BN, B_SZ / BM), 256, SMEM_TOTAL>>>(nullptr);

    // classifier + sigmoid
    final_kernel<<<(B_SZ * 32) / 256, 256>>>(cla_w, cla_b, out);
}

// round 14
// speedup vs baseline: 2.2454x; 2.2454x over previous
#include <cuda_runtime.h>
#include <cuda_fp16.h>
#include <cstdint>

#define B_SZ   8192
#define D_IN   5000
#define H_SZ   512
#define T_SZ   16
#define K1PAD  5120
#define K3     8192

// ---------------- device scratch (static; no runtime allocation) ------------
__device__ __half gA1h[(size_t)B_SZ * K1PAD];
__device__ __half gA1l[(size_t)B_SZ * K1PAD];
__device__ __half gB1h[(size_t)H_SZ * K1PAD];
__device__ __half gB1l[(size_t)H_SZ * K1PAD];
__device__ __half gA3h[(size_t)B_SZ * K3];
__device__ __half gA3l[(size_t)B_SZ * K3];
__device__ __half gB3h[(size_t)H_SZ * K3];
__device__ __half gB3l[(size_t)H_SZ * K3];
__device__ float g_mlp_out[(size_t)B_SZ * H_SZ];
__device__ float g_out1[(size_t)B_SZ * H_SZ];

// ---------------- helpers ----------------------------------------------------
__device__ __forceinline__ uint32_t smem_u32(const void* p) {
    uint32_t a;
    asm("{ .reg .u64 t; cvta.to.shared.u64 t, %1; cvt.u32.u64 %0, t; }"
        : "=r"(a) : "l"(p));
    return a;
}

__device__ __forceinline__ void cpa16(uint32_t d, const void* s) {
    asm volatile("cp.async.cg.shared.global [%0], [%1], 16;" :: "r"(d), "l"(s));
}
#define CP_COMMIT() asm volatile("cp.async.commit_group;" ::: "memory")
#define CP_WAIT1()  asm volatile("cp.async.wait_group 1;" ::: "memory")

__device__ __forceinline__ void ldsm4(uint32_t* r, uint32_t a) {
    asm volatile("ldmatrix.sync.aligned.m8n8.x4.shared.b16 {%0,%1,%2,%3}, [%4];"
                 : "=r"(r[0]), "=r"(r[1]), "=r"(r[2]), "=r"(r[3]) : "r"(a));
}

__device__ __forceinline__ void mma16816(float* c, const uint32_t* a,
                                         uint32_t b0, uint32_t b1) {
    asm volatile(
        "mma.sync.aligned.m16n8k16.row.col.f32.f16.f16.f32 "
        "{%0,%1,%2,%3}, {%4,%5,%6,%7}, {%8,%9}, {%0,%1,%2,%3};"
        : "+f"(c[0]), "+f"(c[1]), "+f"(c[2]), "+f"(c[3])
        : "r"(a[0]), "r"(a[1]), "r"(a[2]), "r"(a[3]), "r"(b0), "r"(b1));
}

// ---------------- split helpers ---------------------------------------------
__device__ __forceinline__ void split4h_store(__half* ph, __half* pl,
                                              size_t off, float4 v) {
    union { __half b[4]; uint2 u; } H, L;
    float x[4] = {v.x, v.y, v.z, v.w};
#pragma unroll
    for (int i = 0; i < 4; ++i) {
        __half h = __float2half_rn(x[i]);
        H.b[i] = h;
        L.b[i] = __float2half_rn(x[i] - __half2float(h));
    }
    *(uint2*)(ph + off) = H.u;
    *(uint2*)(pl + off) = L.u;
}

__device__ __forceinline__ void split2h_store(__half* ph, __half* pl,
                                              size_t off, float a, float b) {
    union { __half h[2]; uint32_t u; } H, L;
    __half ha = __float2half_rn(a);
    __half hb = __float2half_rn(b);
    H.h[0] = ha; H.h[1] = hb;
    L.h[0] = __float2half_rn(a - __half2float(ha));
    L.h[1] = __float2half_rn(b - __half2float(hb));
    *(uint32_t*)(ph + off) = H.u;
    *(uint32_t*)(pl + off) = L.u;
}

// ---------------- prep kernels ----------------------------------------------
__global__ void prep_A1(const float* __restrict__ x) {
    long idx = (long)blockIdx.x * 256 + threadIdx.x;
    int b  = (int)(idx / (K1PAD / 4));
    int c4 = (int)(idx % (K1PAD / 4));
    int c = c4 * 4;
    float4 v = make_float4(0.f, 0.f, 0.f, 0.f);
    if (c < D_IN) v = *(const float4*)(x + (size_t)b * D_IN + c);
    split4h_store(gA1h, gA1l, (size_t)b * K1PAD + c, v);
}

__global__ void prep_B1(const float* __restrict__ w) {
    long idx = (long)blockIdx.x * 256 + threadIdx.x;
    int n  = (int)(idx / (K1PAD / 4));
    int c4 = (int)(idx % (K1PAD / 4));
    int c = c4 * 4;
    float4 v = make_float4(0.f, 0.f, 0.f, 0.f);
    if (c < D_IN) v = *(const float4*)(w + (size_t)n * D_IN + c);
    split4h_store(gB1h, gB1l, (size_t)n * K1PAD + c, v);
}

// CM [K3=8192][H=512] -> gB3 [H=512][K3=8192] (transpose + split)
__global__ void prep_B3(const float* __restrict__ CM) {
    __shared__ float tile[32][33];
    int k0 = blockIdx.x * 32;
    int n0 = blockIdx.y * 32;
    int tx = threadIdx.x, ty = threadIdx.y;
#pragma unroll
    for (int j = 0; j < 32; j += 8)
        tile[ty + j][tx] = CM[(size_t)(k0 + ty + j) * H_SZ + n0 + tx];
    __syncthreads();
#pragma unroll
    for (int j = 0; j < 32; j += 8) {
        float v = tile[tx][ty + j];
        __half h = __float2half_rn(v);
        __half l = __float2half_rn(v - __half2float(h));
        size_t o = (size_t)(n0 + ty + j) * K3 + k0 + tx;
        gB3h[o] = h;
        gB3l[o] = l;
    }
}

// ---------------- HMMA GEMM --------------------------------------------------
// C[M=8192, N=512] = A @ B^T, fp16 split-2 (hi*hi + hi*lo + lo*hi), fp32 acc.
// CTA tile 64x64, BK=32, 3-stage cp.async pipeline, 8 warps (4M x 2N),
// warp tile 16x32. Smem: 64B rows, XOR swizzle (chunk ^= (row>>1)&3).
// Stage 16KB, 3 stages = 48KB -> 3 CTAs/SM (launch_bounds 256,3).
// Grid = 1024 CTAs over 444 slots: finer wave quantization than 512/444.
#define BM 64
#define BN 64
#define BK 32
#define ROWB 64
#define PLANE_A (BM * ROWB)                 // 4096
#define PLANE_B (BN * ROWB)                 // 4096
#define STAGE (2 * PLANE_A + 2 * PLANE_B)   // 16384
#define OFF_AH 0
#define OFF_AL PLANE_A
#define OFF_BH (2 * PLANE_A)
#define OFF_BL (2 * PLANE_A + PLANE_B)
#define NSTAGE 3
#define SMEM_TOTAL (NSTAGE * STAGE)

__device__ __forceinline__ void load_stage(uint32_t st,
                                           const __half* __restrict__ Ah,
                                           const __half* __restrict__ Al,
                                           const __half* __restrict__ Bh,
                                           const __half* __restrict__ Bl,
                                           int m0, int n0, int K, int k0,
                                           int tid) {
    // A: 64 rows x 4 chunks = 256 ops per plane; one per thread
    const int r = tid >> 2;
    const int c = tid & 3;
    const int sw = (r >> 1) & 3;
    const uint32_t o = (uint32_t)r * ROWB + (uint32_t)((c ^ sw) << 4);
    const size_t ga = (size_t)(m0 + r) * K + k0 + c * 8;
    const size_t gb = (size_t)(n0 + r) * K + k0 + c * 8;
    cpa16(st + OFF_AH + o, Ah + ga);
    cpa16(st + OFF_AL + o, Al + ga);
    cpa16(st + OFF_BH + o, Bh + gb);
    cpa16(st + OFF_BL + o, Bl + gb);
}

template <int MODE>
__global__ void __launch_bounds__(256, 3)
gemm_hmma(const float* __restrict__ bias) {
    extern __shared__ char smem[];
    const uint32_t sb = smem_u32(smem);
    const int tid = threadIdx.x;
    const int wid = tid >> 5, lane = tid & 31;
    const int wm = wid >> 1;            // 0..3  (M, 16 rows each)
    const int wn = wid & 1;             // 0..1  (N, 32 cols each)

    const int K  = (MODE == 0) ? K1PAD : K3;
    const int nt = K / BK;
    const __half* Ah = (MODE == 0) ? gA1h : gA3h;
    const __half* Al = (MODE == 0) ? gA1l : gA3l;
    const __half* Bh = (MODE == 0) ? gB1h : gB3h;
    const __half* Bl = (MODE == 0) ? gB1l : gB3l;
    float* __restrict__ C = (MODE == 0) ? g_mlp_out : g_out1;

    const int m0 = blockIdx.y * BM;
    const int n0 = blockIdx.x * BN;

    float acc[4][4];                    // [nb*2+half][4]
#pragma unroll
    for (int j = 0; j < 4; ++j)
#pragma unroll
        for (int q = 0; q < 4; ++q) acc[j][q] = 0.f;

    const int lrow = lane & 15;
    const int lk   = lane >> 4;

    uint32_t aro, asw;
    {
        int row = wm * 16 + lrow;
        aro = (uint32_t)row * ROWB;
        asw = (uint32_t)(((row >> 1) & 3) << 4);
    }
    uint32_t bro[2], bsw[2];
#pragma unroll
    for (int nb = 0; nb < 2; ++nb) {
        int row = wn * 32 + nb * 16 + lrow;
        bro[nb] = (uint32_t)row * ROWB;
        bsw[nb] = (uint32_t)(((row >> 1) & 3) << 4);
    }

    // prologue
    load_stage(sb + 0 * STAGE, Ah, Al, Bh, Bl, m0, n0, K, 0, tid);
    CP_COMMIT();
    load_stage(sb + 1 * STAGE, Ah, Al, Bh, Bl, m0, n0, K, BK, tid);
    CP_COMMIT();

    for (int i = 0; i < nt; ++i) {
        CP_WAIT1();
        __syncthreads();
        const uint32_t st = sb + (uint32_t)(i % NSTAGE) * STAGE;

        if (i + 2 < nt)
            load_stage(sb + (uint32_t)((i + 2) % NSTAGE) * STAGE,
                       Ah, Al, Bh, Bl, m0, n0, K, (i + 2) * BK, tid);
        CP_COMMIT();

#pragma unroll
        for (int ks = 0; ks < 2; ++ks) {
            const uint32_t cid = (uint32_t)((ks * 2 + lk) << 4);
            uint32_t aH[4], aL[4];
            {
                const uint32_t ro = aro + (cid ^ asw);
                ldsm4(aH, st + OFF_AH + ro);
                ldsm4(aL, st + OFF_AL + ro);
            }
#pragma unroll
            for (int nb = 0; nb < 2; ++nb) {
                uint32_t bH[4], bL[4];
                const uint32_t ro = bro[nb] + (cid ^ bsw[nb]);
                ldsm4(bH, st + OFF_BH + ro);
                ldsm4(bL, st + OFF_BL + ro);
                mma16816(acc[nb * 2],     aH, bH[0], bH[2]);
                mma16816(acc[nb * 2 + 1], aH, bH[1], bH[3]);
                mma16816(acc[nb * 2],     aH, bL[0], bL[2]);
                mma16816(acc[nb * 2 + 1], aH, bL[1], bL[3]);
                mma16816(acc[nb * 2],     aL, bH[0], bH[2]);
                mma16816(acc[nb * 2 + 1], aL, bH[1], bH[3]);
            }
        }
    }

    // epilogue
    const int gid = lane >> 2;
    const int tig = lane & 3;
#pragma unroll
    for (int nf = 0; nf < 4; ++nf) {
        const int nb = nf >> 1, half = nf & 1;
        const int row = m0 + wm * 16 + gid;
        const int col = n0 + wn * 32 + nb * 16 + half * 8 + 2 * tig;
        float2 v0 = make_float2(acc[nf][0], acc[nf][1]);
        float2 v1 = make_float2(acc[nf][2], acc[nf][3]);
        if (MODE == 0) {
            v0.x += bias[col]; v0.y += bias[col + 1];
            v1.x += bias[col]; v1.y += bias[col + 1];
        }
        *(float2*)(C + (size_t)row * H_SZ + col)       = v0;
        *(float2*)(C + (size_t)(row + 8) * H_SZ + col) = v1;
    }
}

// ---------------- softmax over tasks + fused A3 build ------------------------
__global__ void attn_softmax_kernel(const float* __restrict__ attn) {
    __shared__ float row[H_SZ];
    __shared__ float s[T_SZ];
    __shared__ float wsh[T_SZ];
    const int b = blockIdx.x;
    const int tid = threadIdx.x;
    ((float2*)row)[tid] = ((const float2*)(g_mlp_out + (size_t)b * H_SZ))[tid];
    __syncthreads();
    const int warp = tid >> 5, lane = tid & 31;
#pragma unroll
    for (int tt = 0; tt < 2; ++tt) {
        const int t = warp * 2 + tt;
        float acc = 0.f;
#pragma unroll 4
        for (int h = lane; h < H_SZ; h += 32) acc += row[h] * attn[h * T_SZ + t];
#pragma unroll
        for (int o = 16; o; o >>= 1) acc += __shfl_xor_sync(0xffffffffu, acc, o);
        if (lane == 0) s[t] = acc;
    }
    __syncthreads();
    if (tid == 0) {
        float mx = s[0];
#pragma unroll
        for (int t = 1; t < T_SZ; ++t) mx = fmaxf(mx, s[t]);
        float e[T_SZ];
        float sum = 0.f;
#pragma unroll
        for (int t = 0; t < T_SZ; ++t) { e[t] = __expf(s[t] - mx); sum += e[t]; }
        float inv = 1.f / sum;
#pragma unroll
        for (int t = 0; t < T_SZ; ++t) wsh[t] = e[t] * inv;
    }
    __syncthreads();
    const float2 m2 = ((const float2*)row)[tid];
    const size_t base = (size_t)b * K3 + 2 * tid;
#pragma unroll
    for (int t = 0; t < T_SZ; ++t) {
        const float wv = wsh[t];
        split2h_store(gA3h, gA3l, base + (size_t)t * H_SZ,
                      m2.x * wv, m2.y * wv);
    }
}

// ---------------- classifier + sigmoid --------------------------------------
__global__ void final_kernel(const float* __restrict__ cla_w,
                             const float* __restrict__ cla_b,
                             float* __restrict__ out) {
    const int gw = (blockIdx.x * blockDim.x + threadIdx.x) >> 5;
    const int lane = threadIdx.x & 31;
    if (gw >= B_SZ) return;
    const float4* rp = (const float4*)(g_out1 + (size_t)gw * H_SZ);
    const float4* wp = (const float4*)cla_w;
    float acc = 0.f;
#pragma unroll
    for (int i = lane; i < H_SZ / 4; i += 32) {
        float4 a = rp[i], w = wp[i];
        acc += a.x * w.x + a.y * w.y + a.z * w.z + a.w * w.w;
    }
#pragma unroll
    for (int o = 16; o; o >>= 1) acc += __shfl_xor_sync(0xffffffffu, acc, o);
    if (lane == 0) {
        float logit = acc + cla_b[0];
        out[gw] = 1.f / (1.f + __expf(-logit));
    }
}

// ---------------- launch -----------------------------------------------------
extern "C" void kernel_launch(void* const* d_in, const int* in_sizes, int n_in,
                              void* d_out, int out_size) {
    const float* data_input = (const float*)d_in[0];
    const float* mlp_w      = (const float*)d_in[1];
    const float* mlp_b      = (const float*)d_in[2];
    const float* CM         = (const float*)d_in[3];
    const float* attn       = (const float*)d_in[4];
    const float* cla_w      = (const float*)d_in[5];
    const float* cla_b      = (const float*)d_in[6];
    float* out = (float*)d_out;

    cudaFuncSetAttribute(gemm_hmma<0>, cudaFuncAttributeMaxDynamicSharedMemorySize,
                         SMEM_TOTAL);
    cudaFuncSetAttribute(gemm_hmma<1>, cudaFuncAttributeMaxDynamicSharedMemorySize,
                         SMEM_TOTAL);

    // input conversions
    prep_A1<<<(B_SZ * (K1PAD / 4)) / 256, 256>>>(data_input);
    prep_B1<<<(H_SZ * (K1PAD / 4)) / 256, 256>>>(mlp_w);
    prep_B3<<<dim3(K3 / 32, H_SZ / 32), dim3(32, 8)>>>(CM);

    // GEMM1: mlp_out = data @ mlp_w^T + b   (grid 8 x 128 = 1024 CTAs)
    gemm_hmma<0><<<dim3(H_SZ / BN, B_SZ / BM), 256, SMEM_TOTAL>>>(mlp_b);

    // softmax task weights + fused A' split build
    attn_softmax_kernel<<<B_SZ, 256>>>(attn);

    // GEMM3: out1 = A' @ CM^T
    gemm_hmma<1><<<dim3(H_SZ / BN, B_SZ / BM), 256, SMEM_TOTAL>>>(nullptr);

    // classifier + sigmoid
    final_kernel<<<(B_SZ * 32) / 256, 256>>>(cla_w, cla_b, out);
}